// round 7
// baseline (speedup 1.0000x reference)
#include <cuda_runtime.h>
#include <cstdint>

// x[256, 4096, 32] -> out[256, 64, 64, 32]  (GADF)
#define BATCH 256
#define TLEN  4096
#define CH    32
#define PAA   64
#define BINSZ 64    // TLEN / PAA
#define SEGS  8     // reduce blocks per batch
#define KPROD 4     // produce blocks per batch
#define LAG   32    // produce for batch b dispatches with reduce for batch b+LAG

// Inter-block scratch (L2-resident) + handoff flags (self-resetting).
__device__ float g_binsum[BATCH][PAA][CH];   // 2 MB
__device__ float g_pmin[BATCH][SEGS][CH];    // 256 KB
__device__ float g_pmax[BATCH][SEGS][CH];    // 256 KB
__device__ int   g_done[BATCH];              // reduce-completion counters (0 -> 8)
__device__ int   g_consumed[BATCH];          // produce-completion counters (0 -> 4)

// Grid layout (3072 blocks, dispatch ~in index order):
//   [0, 256):        reduce batches 0..31                     (pure-read prologue)
//   [256, 2944):     groups of 12: 8 reduce (batch 32+g) + 4 produce (batch g)
//   [2944, 3072):    produce batches 224..255                 (pure-write tail)
// Producer blocks always sit >=768 indices before their consumers and have no
// dependencies themselves -> consumers' spins always terminate.

__device__ __forceinline__ void reduce_role(const float* __restrict__ x,
                                            int b, int s) {
    __shared__ float smn[8][36];
    __shared__ float smx[8][36];

    const int tid   = threadIdx.x;
    const int lane  = tid & 31;
    const int warp  = tid >> 5;          // 0..7
    const int t_off = lane >> 3;         // 0..3
    const int c4    = (lane & 7) * 4;
    const int bin   = 8 * s + warp;

    const float* base = x + (size_t)b * (TLEN * CH)
                          + (size_t)(bin * BINSZ + t_off) * CH + c4;

    float4 sum  = {0, 0, 0, 0};
    float4 vmin = { 3.4e38f,  3.4e38f,  3.4e38f,  3.4e38f};
    float4 vmax = {-3.4e38f, -3.4e38f, -3.4e38f, -3.4e38f};

    #pragma unroll
    for (int k = 0; k < 16; ++k) {
        float4 v = __ldcs((const float4*)(base + (size_t)(4 * k) * CH));
        sum.x += v.x; sum.y += v.y; sum.z += v.z; sum.w += v.w;
        vmin.x = fminf(vmin.x, v.x); vmin.y = fminf(vmin.y, v.y);
        vmin.z = fminf(vmin.z, v.z); vmin.w = fminf(vmin.w, v.w);
        vmax.x = fmaxf(vmax.x, v.x); vmax.y = fmaxf(vmax.y, v.y);
        vmax.z = fmaxf(vmax.z, v.z); vmax.w = fmaxf(vmax.w, v.w);
    }

    #pragma unroll
    for (int o = 8; o <= 16; o <<= 1) {
        sum.x += __shfl_xor_sync(~0u, sum.x, o); sum.y += __shfl_xor_sync(~0u, sum.y, o);
        sum.z += __shfl_xor_sync(~0u, sum.z, o); sum.w += __shfl_xor_sync(~0u, sum.w, o);
        vmin.x = fminf(vmin.x, __shfl_xor_sync(~0u, vmin.x, o));
        vmin.y = fminf(vmin.y, __shfl_xor_sync(~0u, vmin.y, o));
        vmin.z = fminf(vmin.z, __shfl_xor_sync(~0u, vmin.z, o));
        vmin.w = fminf(vmin.w, __shfl_xor_sync(~0u, vmin.w, o));
        vmax.x = fmaxf(vmax.x, __shfl_xor_sync(~0u, vmax.x, o));
        vmax.y = fmaxf(vmax.y, __shfl_xor_sync(~0u, vmax.y, o));
        vmax.z = fmaxf(vmax.z, __shfl_xor_sync(~0u, vmax.z, o));
        vmax.w = fmaxf(vmax.w, __shfl_xor_sync(~0u, vmax.w, o));
    }

    if (t_off == 0) {  // lanes 0..7 hold channels c4..c4+3
        *(float4*)&g_binsum[b][bin][c4] = sum;
        *(float4*)&smn[warp][c4] = vmin;
        *(float4*)&smx[warp][c4] = vmax;
    }
    __syncthreads();

    if (tid < CH) {
        float m = smn[0][tid], M = smx[0][tid];
        #pragma unroll
        for (int w = 1; w < 8; ++w) {
            m = fminf(m, smn[w][tid]);
            M = fmaxf(M, smx[w][tid]);
        }
        g_pmin[b][s][tid] = m;
        g_pmax[b][s][tid] = M;
    }

    // Publish: all stores visible before the flag increment.
    __threadfence();
    __syncthreads();
    if (tid == 0) atomicAdd(&g_done[b], 1);
}

__device__ __forceinline__ void produce_role(float* __restrict__ out,
                                             int b, int sub) {
    __shared__ float sp[PAA][CH];    // p
    __shared__ float sy[PAA][CH];    // y
    __shared__ float smin[CH];
    __shared__ float sinv[CH];

    const int tid = threadIdx.x;

    // Wait for all 8 reduce blocks of batch b (producers never wait -> no deadlock).
    if (tid == 0) {
        volatile int* df = g_done;
        while (df[b] < SEGS) { }
        __threadfence();
    }
    __syncthreads();

    if (tid < CH) {
        float m = g_pmin[b][0][tid], M = g_pmax[b][0][tid];
        #pragma unroll
        for (int s = 1; s < SEGS; ++s) {
            m = fminf(m, g_pmin[b][s][tid]);
            M = fmaxf(M, g_pmax[b][s][tid]);
        }
        smin[tid] = m;
        sinv[tid] = 1.0f / (M - m);
    }
    __syncthreads();

    #pragma unroll
    for (int idx = tid; idx < PAA * CH; idx += 256) {
        int c = idx & (CH - 1);
        float pv = ((&g_binsum[b][0][0])[idx] * (1.0f / BINSZ) - smin[c]) * sinv[c];
        (&sp[0][0])[idx] = pv;
        (&sy[0][0])[idx] = sqrtf(fmaxf(0.0f, 1.0f - pv * pv));
    }
    __syncthreads();

    // Write 16 i-rows (128 KB): thread -> (j0 = tid>>3 in [0,32), c4),
    // handles j0 and j0+32; STG.128, 512B contiguous per warp.
    const int c4 = (tid & 7) * 4;
    const int j0 = tid >> 3;

    const float4 pj0 = *(const float4*)&sp[j0][c4];
    const float4 yj0 = *(const float4*)&sy[j0][c4];
    const float4 pj1 = *(const float4*)&sp[j0 + 32][c4];
    const float4 yj1 = *(const float4*)&sy[j0 + 32][c4];

    float* ob = out + (size_t)b * (PAA * PAA * CH) + c4;
    #pragma unroll 4
    for (int ii = 0; ii < 16; ++ii) {
        const int i = sub * 16 + ii;
        const float4 pi = *(const float4*)&sp[i][c4];   // broadcast x4
        const float4 yi = *(const float4*)&sy[i][c4];
        float* orow = ob + (size_t)i * (PAA * CH);

        float4 o0;
        o0.x = yi.x * pj0.x - pi.x * yj0.x;
        o0.y = yi.y * pj0.y - pi.y * yj0.y;
        o0.z = yi.z * pj0.z - pi.z * yj0.z;
        o0.w = yi.w * pj0.w - pi.w * yj0.w;
        __stcs((float4*)(orow + (size_t)j0 * CH), o0);

        float4 o1;
        o1.x = yi.x * pj1.x - pi.x * yj1.x;
        o1.y = yi.y * pj1.y - pi.y * yj1.y;
        o1.z = yi.z * pj1.z - pi.z * yj1.z;
        o1.w = yi.w * pj1.w - pi.w * yj1.w;
        __stcs((float4*)(orow + (size_t)(j0 + 32) * CH), o1);
    }

    // Self-reset counters for the next graph replay. All KPROD consumers have
    // passed the spin before the last one resets (consumed increments happen
    // strictly after each block's spin).
    __syncthreads();
    if (tid == 0) {
        int old = atomicAdd(&g_consumed[b], 1);
        if (old == KPROD - 1) {
            atomicExch(&g_done[b], 0);
            atomicExch(&g_consumed[b], 0);
        }
    }
}

__global__ __launch_bounds__(256)
void gaf_overlap_kernel(const float* __restrict__ x, float* __restrict__ out) {
    const int bid = blockIdx.x;
    if (bid < 256) {
        reduce_role(x, bid >> 3, bid & 7);
    } else if (bid < 2944) {
        const int t = bid - 256;
        const int g = t / 12;
        const int r = t - g * 12;
        if (r < 8) reduce_role(x, LAG + g, r);
        else       produce_role(out, g, r - 8);
    } else {
        const int t = bid - 2944;
        produce_role(out, 224 + (t >> 2), t & 3);
    }
}

extern "C" void kernel_launch(void* const* d_in, const int* in_sizes, int n_in,
                              void* d_out, int out_size) {
    const float* x = (const float*)d_in[0];
    float* out = (float*)d_out;
    gaf_overlap_kernel<<<BATCH * SEGS + BATCH * KPROD, 256>>>(x, out);
}

// round 8
// speedup vs baseline: 1.0596x; 1.0596x over previous
#include <cuda_runtime.h>

// x[256, 4096, 32] -> out[256, 64, 64, 32]  (GADF)
#define BATCH 256
#define TLEN  4096
#define CH    32
#define PAA   64
#define BINSZ 64   // TLEN / PAA

// One block per batch element, 1024 threads = 32 warps (2 CTAs/SM).
// Read phase: warp w owns t in [128w,128w+128); lane -> (t_off=lane>>3,
//   c4=(lane&7)*4); 32 x LDG.128 (512B/warp/instr); 2 bin sums + min/max
//   in float4 regs; xor-8/16 shuffles collapse the 4 t_off copies.
// Write phase: thread owns (c4, j, i0); i += 2, software-pipelined:
//   LDS for iteration k+1 issues before FMA/STG of iteration k, so the
//   29-cyc LDS latency is hidden (fits the 32-reg cap: pj/yj 8 + cur 8 +
//   next 8 + out 4 + addressing).
__global__ __launch_bounds__(1024, 2)
void gaf_gadf_kernel(const float* __restrict__ x, float* __restrict__ out) {
    __shared__ float sp[PAA][CH];      // bin sums -> p   (8 KB)
    __shared__ float sy[PAA][CH];      // y               (8 KB)
    __shared__ float smmn[32][36];     // per-warp per-channel min
    __shared__ float smmx[32][36];
    __shared__ float smin[CH];
    __shared__ float smax[CH];

    const int tid   = threadIdx.x;
    const int lane  = tid & 31;
    const int warp  = tid >> 5;        // 0..31
    const int t_off = lane >> 3;       // 0..3
    const int c4    = (lane & 7) * 4;  // channel group start
    const int b     = blockIdx.x;

    const float* xb = x + (size_t)b * (TLEN * CH);

    // ---------------- Read phase ----------------
    {
        const float* base = xb + (size_t)(128 * warp + t_off) * CH + c4;
        float4 s0 = {0,0,0,0}, s1 = {0,0,0,0};
        float4 vmin = { 3.4e38f,  3.4e38f,  3.4e38f,  3.4e38f};
        float4 vmax = {-3.4e38f, -3.4e38f, -3.4e38f, -3.4e38f};

        #pragma unroll 8
        for (int k = 0; k < 16; ++k) {
            float4 v = __ldcs((const float4*)(base + (size_t)(4 * k) * CH));
            s0.x += v.x; s0.y += v.y; s0.z += v.z; s0.w += v.w;
            vmin.x = fminf(vmin.x, v.x); vmin.y = fminf(vmin.y, v.y);
            vmin.z = fminf(vmin.z, v.z); vmin.w = fminf(vmin.w, v.w);
            vmax.x = fmaxf(vmax.x, v.x); vmax.y = fmaxf(vmax.y, v.y);
            vmax.z = fmaxf(vmax.z, v.z); vmax.w = fmaxf(vmax.w, v.w);
        }
        #pragma unroll 8
        for (int k = 16; k < 32; ++k) {
            float4 v = __ldcs((const float4*)(base + (size_t)(4 * k) * CH));
            s1.x += v.x; s1.y += v.y; s1.z += v.z; s1.w += v.w;
            vmin.x = fminf(vmin.x, v.x); vmin.y = fminf(vmin.y, v.y);
            vmin.z = fminf(vmin.z, v.z); vmin.w = fminf(vmin.w, v.w);
            vmax.x = fmaxf(vmax.x, v.x); vmax.y = fmaxf(vmax.y, v.y);
            vmax.z = fmaxf(vmax.z, v.z); vmax.w = fmaxf(vmax.w, v.w);
        }

        #pragma unroll
        for (int o = 8; o <= 16; o <<= 1) {
            s0.x += __shfl_xor_sync(~0u, s0.x, o); s0.y += __shfl_xor_sync(~0u, s0.y, o);
            s0.z += __shfl_xor_sync(~0u, s0.z, o); s0.w += __shfl_xor_sync(~0u, s0.w, o);
            s1.x += __shfl_xor_sync(~0u, s1.x, o); s1.y += __shfl_xor_sync(~0u, s1.y, o);
            s1.z += __shfl_xor_sync(~0u, s1.z, o); s1.w += __shfl_xor_sync(~0u, s1.w, o);
            vmin.x = fminf(vmin.x, __shfl_xor_sync(~0u, vmin.x, o));
            vmin.y = fminf(vmin.y, __shfl_xor_sync(~0u, vmin.y, o));
            vmin.z = fminf(vmin.z, __shfl_xor_sync(~0u, vmin.z, o));
            vmin.w = fminf(vmin.w, __shfl_xor_sync(~0u, vmin.w, o));
            vmax.x = fmaxf(vmax.x, __shfl_xor_sync(~0u, vmax.x, o));
            vmax.y = fmaxf(vmax.y, __shfl_xor_sync(~0u, vmax.y, o));
            vmax.z = fmaxf(vmax.z, __shfl_xor_sync(~0u, vmax.z, o));
            vmax.w = fmaxf(vmax.w, __shfl_xor_sync(~0u, vmax.w, o));
        }
        if (t_off == 0) {
            *(float4*)&sp[2 * warp + 0][c4] = s0;
            *(float4*)&sp[2 * warp + 1][c4] = s1;
            *(float4*)&smmn[warp][c4] = vmin;
            *(float4*)&smmx[warp][c4] = vmax;
        }
    }
    __syncthreads();

    // ---------------- Final min/max over 32 warps ----------------
    if (tid < CH) {
        float m = smmn[0][tid], M = smmx[0][tid];
        #pragma unroll
        for (int w = 1; w < 32; ++w) {
            m = fminf(m, smmn[w][tid]);
            M = fmaxf(M, smmx[w][tid]);
        }
        smin[tid] = m;
        smax[tid] = M;
    }
    __syncthreads();

    // ---------------- p and y ----------------
    {
        int idx = tid;
        #pragma unroll
        for (int r = 0; r < 2; ++r, idx += 1024) {
            int c = idx & (CH - 1);
            float mn  = smin[c];
            float inv = 1.0f / (smax[c] - mn);
            float pv  = ((&sp[0][0])[idx] * (1.0f / BINSZ) - mn) * inv;
            (&sp[0][0])[idx] = pv;
            (&sy[0][0])[idx] = sqrtf(fmaxf(0.0f, 1.0f - pv * pv));
        }
    }
    __syncthreads();

    // ---------------- Write phase (software-pipelined LDS) ----------------
    const int j  = (tid >> 3) & 63;
    const int i0 = tid >> 9;           // 0 or 1; i strides by 2

    const float4 pj = *(const float4*)&sp[j][c4];
    const float4 yj = *(const float4*)&sy[j][c4];

    float* ob = out + (size_t)b * (PAA * PAA * CH) + (size_t)j * CH + c4;

    // Prologue: load iteration 0's operands.
    float4 pi = *(const float4*)&sp[i0][c4];
    float4 yi = *(const float4*)&sy[i0][c4];

    #pragma unroll 4
    for (int i = i0; i < PAA - 2; i += 2) {
        // Prefetch next iteration's operands first — STG below never waits
        // on its own LDS.
        const float4 pn = *(const float4*)&sp[i + 2][c4];
        const float4 yn = *(const float4*)&sy[i + 2][c4];

        float4 o;
        o.x = yi.x * pj.x - pi.x * yj.x;
        o.y = yi.y * pj.y - pi.y * yj.y;
        o.z = yi.z * pj.z - pi.z * yj.z;
        o.w = yi.w * pj.w - pi.w * yj.w;
        __stcs((float4*)(ob + (size_t)i * (PAA * CH)), o);

        pi = pn; yi = yn;
    }
    // Epilogue: last iteration (i = 62 + i0).
    {
        const int i = PAA - 2 + i0;
        float4 o;
        o.x = yi.x * pj.x - pi.x * yj.x;
        o.y = yi.y * pj.y - pi.y * yj.y;
        o.z = yi.z * pj.z - pi.z * yj.z;
        o.w = yi.w * pj.w - pi.w * yj.w;
        __stcs((float4*)(ob + (size_t)i * (PAA * CH)), o);
    }
}

extern "C" void kernel_launch(void* const* d_in, const int* in_sizes, int n_in,
                              void* d_out, int out_size) {
    const float* x = (const float*)d_in[0];
    float* out = (float*)d_out;
    gaf_gadf_kernel<<<BATCH, 1024>>>(x, out);
}

// round 9
// speedup vs baseline: 1.1180x; 1.0552x over previous
#include <cuda_runtime.h>

// x[256, 4096, 32] -> out[256, 64, 64, 32]  (GADF)
#define BATCH 256
#define TLEN  4096
#define CH    32
#define PAA   64
#define BINSZ 64   // TLEN / PAA

// One block per batch element, 1024 threads = 32 warps (2 CTAs/SM).
// Read phase: warp w owns t in [128w,128w+128); lane -> (t_off=lane>>3,
//   c4=(lane&7)*4); 32 x LDG.128 streaming (512B/warp/instr); 2 bin sums +
//   min/max in float4 regs; xor-8/16 shuffles collapse the 4 t_off copies.
// Write phase: default write-back STG.128 (NOT streaming) — output sits
//   dirty in L2 and drains lazily, overlapping the next replay's read phase.
__global__ __launch_bounds__(1024, 2)
void gaf_gadf_kernel(const float* __restrict__ x, float* __restrict__ out) {
    __shared__ float sp[PAA][CH];      // bin sums -> p   (8 KB)
    __shared__ float sy[PAA][CH];      // y               (8 KB)
    __shared__ float smmn[32][36];     // per-warp per-channel min
    __shared__ float smmx[32][36];
    __shared__ float smin[CH];
    __shared__ float smax[CH];

    const int tid   = threadIdx.x;
    const int lane  = tid & 31;
    const int warp  = tid >> 5;        // 0..31
    const int t_off = lane >> 3;       // 0..3
    const int c4    = (lane & 7) * 4;  // channel group start
    const int b     = blockIdx.x;

    const float* xb = x + (size_t)b * (TLEN * CH);

    // ---------------- Read phase ----------------
    {
        const float* base = xb + (size_t)(128 * warp + t_off) * CH + c4;
        float4 s0 = {0,0,0,0}, s1 = {0,0,0,0};
        float4 vmin = { 3.4e38f,  3.4e38f,  3.4e38f,  3.4e38f};
        float4 vmax = {-3.4e38f, -3.4e38f, -3.4e38f, -3.4e38f};

        #pragma unroll 8
        for (int k = 0; k < 16; ++k) {
            float4 v = __ldcs((const float4*)(base + (size_t)(4 * k) * CH));
            s0.x += v.x; s0.y += v.y; s0.z += v.z; s0.w += v.w;
            vmin.x = fminf(vmin.x, v.x); vmin.y = fminf(vmin.y, v.y);
            vmin.z = fminf(vmin.z, v.z); vmin.w = fminf(vmin.w, v.w);
            vmax.x = fmaxf(vmax.x, v.x); vmax.y = fmaxf(vmax.y, v.y);
            vmax.z = fmaxf(vmax.z, v.z); vmax.w = fmaxf(vmax.w, v.w);
        }
        #pragma unroll 8
        for (int k = 16; k < 32; ++k) {
            float4 v = __ldcs((const float4*)(base + (size_t)(4 * k) * CH));
            s1.x += v.x; s1.y += v.y; s1.z += v.z; s1.w += v.w;
            vmin.x = fminf(vmin.x, v.x); vmin.y = fminf(vmin.y, v.y);
            vmin.z = fminf(vmin.z, v.z); vmin.w = fminf(vmin.w, v.w);
            vmax.x = fmaxf(vmax.x, v.x); vmax.y = fmaxf(vmax.y, v.y);
            vmax.z = fmaxf(vmax.z, v.z); vmax.w = fmaxf(vmax.w, v.w);
        }

        #pragma unroll
        for (int o = 8; o <= 16; o <<= 1) {
            s0.x += __shfl_xor_sync(~0u, s0.x, o); s0.y += __shfl_xor_sync(~0u, s0.y, o);
            s0.z += __shfl_xor_sync(~0u, s0.z, o); s0.w += __shfl_xor_sync(~0u, s0.w, o);
            s1.x += __shfl_xor_sync(~0u, s1.x, o); s1.y += __shfl_xor_sync(~0u, s1.y, o);
            s1.z += __shfl_xor_sync(~0u, s1.z, o); s1.w += __shfl_xor_sync(~0u, s1.w, o);
            vmin.x = fminf(vmin.x, __shfl_xor_sync(~0u, vmin.x, o));
            vmin.y = fminf(vmin.y, __shfl_xor_sync(~0u, vmin.y, o));
            vmin.z = fminf(vmin.z, __shfl_xor_sync(~0u, vmin.z, o));
            vmin.w = fminf(vmin.w, __shfl_xor_sync(~0u, vmin.w, o));
            vmax.x = fmaxf(vmax.x, __shfl_xor_sync(~0u, vmax.x, o));
            vmax.y = fmaxf(vmax.y, __shfl_xor_sync(~0u, vmax.y, o));
            vmax.z = fmaxf(vmax.z, __shfl_xor_sync(~0u, vmax.z, o));
            vmax.w = fmaxf(vmax.w, __shfl_xor_sync(~0u, vmax.w, o));
        }
        if (t_off == 0) {  // lanes 0..7: channels c4..c4+3
            *(float4*)&sp[2 * warp + 0][c4] = s0;
            *(float4*)&sp[2 * warp + 1][c4] = s1;
            *(float4*)&smmn[warp][c4] = vmin;
            *(float4*)&smmx[warp][c4] = vmax;
        }
    }
    __syncthreads();

    // ---------------- Final min/max over 32 warps ----------------
    if (tid < CH) {
        float m = smmn[0][tid], M = smmx[0][tid];
        #pragma unroll
        for (int w = 1; w < 32; ++w) {
            m = fminf(m, smmn[w][tid]);
            M = fmaxf(M, smmx[w][tid]);
        }
        smin[tid] = m;
        smax[tid] = M;
    }
    __syncthreads();

    // ---------------- p and y ----------------
    {
        int idx = tid;
        #pragma unroll
        for (int r = 0; r < 2; ++r, idx += 1024) {
            int c = idx & (CH - 1);
            float mn  = smin[c];
            float inv = 1.0f / (smax[c] - mn);
            float pv  = ((&sp[0][0])[idx] * (1.0f / BINSZ) - mn) * inv;
            (&sp[0][0])[idx] = pv;
            (&sy[0][0])[idx] = sqrtf(fmaxf(0.0f, 1.0f - pv * pv));
        }
    }
    __syncthreads();

    // ---------------- Write phase: default write-back stores ----------
    const int j  = (tid >> 3) & 63;
    const int i0 = tid >> 9;           // 0 or 1; i strides by 2

    const float4 pj = *(const float4*)&sp[j][c4];
    const float4 yj = *(const float4*)&sy[j][c4];

    float* ob = out + (size_t)b * (PAA * PAA * CH) + (size_t)j * CH + c4;
    #pragma unroll 4
    for (int i = i0; i < PAA; i += 2) {
        const float4 pi = *(const float4*)&sp[i][c4];   // 8 addrs, broadcast x4
        const float4 yi = *(const float4*)&sy[i][c4];
        float4 o;
        o.x = yi.x * pj.x - pi.x * yj.x;
        o.y = yi.y * pj.y - pi.y * yj.y;
        o.z = yi.z * pj.z - pi.z * yj.z;
        o.w = yi.w * pj.w - pi.w * yj.w;
        *(float4*)(ob + (size_t)i * (PAA * CH)) = o;    // write-back STG.128
    }
}

extern "C" void kernel_launch(void* const* d_in, const int* in_sizes, int n_in,
                              void* d_out, int out_size) {
    const float* x = (const float*)d_in[0];
    float* out = (float*)d_out;
    gaf_gadf_kernel<<<BATCH, 1024>>>(x, out);
}